// round 15
// baseline (speedup 1.0000x reference)
#include <cuda_runtime.h>
#include <math.h>
#include <stdint.h>

#define EPSF 1e-6f
#define NBATCH 4096
#define RS3 32            // row stride for 32-row tiles

// k-major repacked weights + TWO zero pad-chunks (2048 floats) each for
// unconditional depth-2 chunk prefetch. W1 padded to 120 k-rows.
__device__ float g_W1c[120 * 256 + 2048];
__device__ float g_W2c[256 * 128 + 2048];
// En / logit scratch (softmax done in finalize kernel)
__device__ float g_en[NBATCH * 64 * 2];
__device__ float g_lg[NBATCH * 64];

// ---------------------------------------------------------------------------
__device__ __forceinline__ float2 ffma2(float2 a, float2 b, float2 c) {
    float2 d;
    asm("fma.rn.f32x2 %0, %1, %2, %3;"
        : "=l"(reinterpret_cast<unsigned long long&>(d))
        : "l"(reinterpret_cast<unsigned long long&>(a)),
          "l"(reinterpret_cast<unsigned long long&>(b)),
          "l"(reinterpret_cast<unsigned long long&>(c)));
    return d;
}

__device__ __forceinline__ float my_sinf(float x) {
    float k = rintf(x * 0.318309886183790672f);
    float r = fmaf(k, -3.14159274101257324f, x);
    r = fmaf(k, 8.742278012618954e-8f, r);
    float r2 = r * r;
    float p = -2.50521083854e-08f;
    p = fmaf(p, r2, 2.75573192239e-06f);
    p = fmaf(p, r2, -1.98412698413e-04f);
    p = fmaf(p, r2, 8.33333333333e-03f);
    p = fmaf(p, r2, -1.66666666667e-01f);
    float s = fmaf(p * r2, r, r);
    int ki = __float2int_rn(k);
    return (ki & 1) ? -s : s;
}

__device__ __forceinline__ float leaky_f(float x) { return x >= 0.f ? x : 0.1f * x; }

// ---------------------------------------------------------------------------
__global__ void repack_kernel(const float* __restrict__ W1,
                              const float* __restrict__ W2)
{
    int idx = blockIdx.x * 256 + threadIdx.x;
    if (idx < 120 * 256 + 2048) {
        int k = idx >> 8, o = idx & 255;
        g_W1c[idx] = (k < 114) ? W1[o * 114 + k] : 0.f;
    }
    if (idx < 256 * 128 + 2048) {
        int k = idx >> 7, o = idx & 127;
        g_W2c[idx] = (k < 256) ? W2[o * 256 + k] : 0.f;
    }
}

// ---------------------------------------------------------------------------
// feature helpers (stride RS3)
// ---------------------------------------------------------------------------
__device__ __forceinline__ void aug_poly(float* __restrict__ Acol, int base,
                                         float dx, float dy)
{
    Acol[(base+0)*RS3] = dx;
    Acol[(base+1)*RS3] = dy;
    float sqx = dx*dx + EPSF, sqy = dy*dy + EPSF;
    float cbx = dx*dx*dx + EPSF, cby = dy*dy*dy + EPSF;
    float exx = __expf(dx) + EPSF, exy = __expf(dy) + EPSF;
    Acol[(base+19)*RS3] = sqx;  Acol[(base+20)*RS3] = sqy;
    Acol[(base+21)*RS3] = cbx;  Acol[(base+22)*RS3] = cby;
    Acol[(base+23)*RS3] = exx;  Acol[(base+24)*RS3] = exy;
    Acol[(base+25)*RS3] = 1.0f / (dx + EPSF);
    Acol[(base+26)*RS3] = 1.0f / (dy + EPSF);
    Acol[(base+44)*RS3] = 1.0f / sqx;  Acol[(base+45)*RS3] = 1.0f / sqy;
    Acol[(base+46)*RS3] = 1.0f / cbx;  Acol[(base+47)*RS3] = 1.0f / cby;
    Acol[(base+48)*RS3] = 1.0f / exx;  Acol[(base+49)*RS3] = 1.0f / exy;
}

__device__ __forceinline__ void aug_sin(float* __restrict__ Acol, int base,
                                        float dx, float dy,
                                        const float* __restrict__ W_s1,
                                        const float* __restrict__ b_s1,
                                        int j0, int j1)
{
    #pragma unroll 1
    for (int j = j0; j < j1; j++) {
        float arg = fmaf(dx, __ldg(W_s1 + 2*j),
                    fmaf(dy, __ldg(W_s1 + 2*j + 1), __ldg(b_s1 + j)));
        float s = my_sinf(arg) + EPSF;
        Acol[(base+2+j)*RS3]  = s;
        Acol[(base+27+j)*RS3] = 1.0f / s;
    }
}

// ---------------------------------------------------------------------------
// Staged GEMM (32-row tile, 128 threads): weights double-buffered in smem,
// chunk = CH k-rows = 1024 floats (2 float4 stage ops/thread).
// DEPTH-2 register prefetch: LDG for chunk c+2 issued at top of iter c;
// chunk c+1 (loaded last iter) is STS'd at the end of iter c. LDG->STS
// distance ~2 chunk bodies (~512 cyc) > DRAM latency.
// rt = tid&7 owns rows 4rt..4rt+3 (1 LDS.128/k); ot = tid>>3 in [0,16)
// owns outs ot*TO..+TO-1 (broadcast LDS). Wg has 2 zero pad-chunks.
// ---------------------------------------------------------------------------
template<int KP, int TO, int CH, int LDWC>
__device__ __forceinline__ void gemm128(const float* At,
                                        const float* __restrict__ Wg,
                                        const float* __restrict__ bg,
                                        float* Ct,
                                        float* __restrict__ wbuf,
                                        int rt, int ot, int tid)
{
    constexpr int NC  = KP / CH;
    constexpr int CHW = CH * LDWC;          // 1024 floats per chunk
    constexpr int NST = CHW / (4 * 128);    // 2 float4 stage ops per thread
    float2 acc[2][TO];
    #pragma unroll
    for (int i = 0; i < TO; i++) {
        float bo = __ldg(bg + ot*TO + i);
        acc[0][i] = make_float2(bo, bo);
        acc[1][i] = make_float2(bo, bo);
    }

    // prologue: stage chunk 0 synchronously; issue LDG for chunk 1
    #pragma unroll
    for (int s = 0; s < NST; s++) {
        float4 st = __ldg(reinterpret_cast<const float4*>(Wg) + s*128 + tid);
        *(reinterpret_cast<float4*>(wbuf) + s*128 + tid) = st;
    }
    float4 nxA[NST];
    #pragma unroll
    for (int s = 0; s < NST; s++)
        nxA[s] = __ldg(reinterpret_cast<const float4*>(Wg + CHW) + s*128 + tid);
    __syncthreads();

    #pragma unroll 1
    for (int c = 0; c < NC; c++) {
        // issue LDG for chunk c+2 (pad-chunks guarantee in-bounds)
        float4 nxB[NST];
        #pragma unroll
        for (int s = 0; s < NST; s++)
            nxB[s] = __ldg(reinterpret_cast<const float4*>(Wg + (c+2)*CHW) + s*128 + tid);

        const float* wb = wbuf + (c & 1)*CHW + ot*TO;
        const float* xk = At + (c*CH)*RS3 + 4*rt;

        #pragma unroll
        for (int k = 0; k < CH; k++) {
            float4 xv = *reinterpret_cast<const float4*>(xk + k*RS3);
            float w[TO];
            #pragma unroll
            for (int i = 0; i < TO/4; i++) {
                float4 t = *reinterpret_cast<const float4*>(wb + k*LDWC + 4*i);
                w[4*i+0] = t.x; w[4*i+1] = t.y; w[4*i+2] = t.z; w[4*i+3] = t.w;
            }
            float2 p0 = make_float2(xv.x, xv.y);
            float2 p1 = make_float2(xv.z, xv.w);
            #pragma unroll
            for (int i = 0; i < TO; i++) {
                float2 ws = make_float2(w[i], w[i]);
                acc[0][i] = ffma2(p0, ws, acc[0][i]);
                acc[1][i] = ffma2(p1, ws, acc[1][i]);
            }
        }

        // store chunk c+1 (loaded a full iteration ago; scoreboard long drained)
        #pragma unroll
        for (int s = 0; s < NST; s++) {
            *(reinterpret_cast<float4*>(wbuf + ((c + 1) & 1)*CHW) + s*128 + tid) = nxA[s];
            nxA[s] = nxB[s];
        }
        __syncthreads();
    }

    // epilogue: leaky + 1 STS.128 per out
    #pragma unroll
    for (int i = 0; i < TO; i++) {
        float4 v;
        v.x = leaky_f(acc[0][i].x);
        v.y = leaky_f(acc[0][i].y);
        v.z = leaky_f(acc[1][i].x);
        v.w = leaky_f(acc[1][i].y);
        *reinterpret_cast<float4*>(Ct + (ot*TO + i)*RS3 + 4*rt) = v;
    }
}

// smem layout (floats): At (features 120x32 = 3840, layer3 partials later),
// h1T 256x32 = 8192 (h2T 128x32 overlays it in layer2 epilogue),
// wbuf 2x1024 = 2048. Total 14080 floats = 56320 B -> 4 CTAs/SM.
#define SM_A    0
#define SM_H1   3840
#define SM_WB   (SM_H1 + 8192)
#define SM_TOT  (SM_WB + 2048)

__global__ void __launch_bounds__(128, 4)
en_kernel(const float* __restrict__ Pn,  const float* __restrict__ Pego,
          const float* __restrict__ Vn,  const float* __restrict__ Vego,
          const float* __restrict__ Cn,
          const float* __restrict__ W_s1, const float* __restrict__ b_s1,
          const float* __restrict__ b1,
          const float* __restrict__ b2,
          const float* __restrict__ W3,  const float* __restrict__ b3,
          const float* __restrict__ Ww,  const float* __restrict__ bw)
{
    extern __shared__ float sm[];
    float* At   = sm + SM_A;
    float* h1T  = sm + SM_H1;     // h1; h2T overlays after layer2
    float* wbuf = sm + SM_WB;

    int tid = threadIdx.x;
    int blk = blockIdx.x;          // 32-row tile: rows [blk*32, blk*32+32)

    // ---- phase 0: features, 4 threads per row ----
    {
        int r = tid >> 2;          // local row 0..31
        int part = tid & 3;
        int gr = blk*32 + r;       // global row = b*64 + n
        int b = gr >> 6;
        int idx2 = gr * 2;
        float* Acol = At + r;
        if (part < 2) {
            float pex = Pego[b*2], pey = Pego[b*2+1];
            float pnx = Pn[idx2],  pny = Pn[idx2+1];
            float dx = pnx - pex,  dy = pny - pey;
            if (part == 0) {
                Acol[0*RS3] = pex;  Acol[1*RS3] = pey;
                Acol[2*RS3] = pnx;  Acol[3*RS3] = pny;
                Acol[4*RS3] = dx;   Acol[5*RS3] = dy;
                Acol[112*RS3] = Cn[idx2];
                Acol[113*RS3] = Cn[idx2+1];
                aug_poly(Acol, 6, dx, dy);
                aug_sin(Acol, 6, dx, dy, W_s1, b_s1, 0, 9);
            } else {
                aug_sin(Acol, 6, dx, dy, W_s1, b_s1, 9, 17);
            }
        } else {
            float vex = Vego[b*2], vey = Vego[b*2+1];
            float vnx = Vn[idx2],  vny = Vn[idx2+1];
            float dx = vnx - vex,  dy = vny - vey;
            if (part == 2) {
                Acol[56*RS3] = vex;  Acol[57*RS3] = vey;
                Acol[58*RS3] = vnx;  Acol[59*RS3] = vny;
                Acol[60*RS3] = dx;   Acol[61*RS3] = dy;
                aug_poly(Acol, 62, dx, dy);
                aug_sin(Acol, 62, dx, dy, W_s1, b_s1, 0, 9);
            } else {
                aug_sin(Acol, 62, dx, dy, W_s1, b_s1, 9, 17);
            }
        }
        // zero pad rows 114..119 (6*32 = 192 entries, contiguous)
        for (int i = tid; i < 192; i += 128)
            At[114*RS3 + i] = 0.f;
    }
    __syncthreads();

    int rt = tid & 7;      // 8 row-groups (4 rows each)
    int ot = tid >> 3;     // 16 out-groups

    // ---- layer1: [32,114(+6 pad)] -> [32,256], leaky (TO=16, CH=4) ----
    gemm128<120, 16, 4, 256>(At, g_W1c, b1, h1T, wbuf, rt, ot, tid);
    __syncthreads();

    // ---- layer2: [32,256] -> [32,128], leaky (TO=8, CH=8); h2T overlays h1T ----
    gemm128<256, 8, 8, 128>(h1T, g_W2c, b2, h1T, wbuf, rt, ot, tid);
    __syncthreads();

    // ---- layer3: 128 threads (4 k-segments x 32 rows), partials in At ----
    {
        int seg = tid >> 5;        // 0..3
        int r   = tid & 31;
        int k0  = seg * 32;
        float a0 = 0.f, a1 = 0.f;
        #pragma unroll 8
        for (int k = k0; k < k0 + 32; k++) {
            float h = h1T[k*RS3 + r];
            a0 = fmaf(h, __ldg(W3 + k),       a0);
            a1 = fmaf(h, __ldg(W3 + 128 + k), a1);
        }
        At[(seg*32 + r)*2]     = a0;
        At[(seg*32 + r)*2 + 1] = a1;
    }
    __syncthreads();

    // ---- layer3 reduce + logits -> global scratch ----
    if (tid < 32) {
        int r = tid;
        float a0 = __ldg(b3), a1 = __ldg(b3 + 1);
        #pragma unroll
        for (int seg = 0; seg < 4; seg++) {
            a0 += At[(seg*32 + r)*2];
            a1 += At[(seg*32 + r)*2 + 1];
        }
        int gr = blk*32 + r;
        int b = gr >> 6;
        int idx2 = gr * 2;
        float pnx = Pn[idx2], pny = Pn[idx2+1];
        float dx = pnx - Pego[b*2], dy = pny - Pego[b*2+1];
        float lg = __ldg(bw);
        lg = fmaf(__ldg(Ww+0), a0,  lg);
        lg = fmaf(__ldg(Ww+1), a1,  lg);
        lg = fmaf(__ldg(Ww+2), pnx, lg);
        lg = fmaf(__ldg(Ww+3), pny, lg);
        lg = fmaf(__ldg(Ww+4), dx,  lg);
        lg = fmaf(__ldg(Ww+5), dy,  lg);
        g_en[gr*2]     = a0;
        g_en[gr*2 + 1] = a1;
        g_lg[gr]       = lg;
    }
}

// ---------------------------------------------------------------------------
// finalize: per-batch softmax over 64 neighbors (1 warp/batch) + Er head
// ---------------------------------------------------------------------------
__global__ void __launch_bounds__(256)
finalize_kernel(const float* __restrict__ ego_y,
                const float* __restrict__ W_sel, const float* __restrict__ b_sel,
                const float* __restrict__ W_s0,  const float* __restrict__ b_s0,
                const float* __restrict__ W_map, const float* __restrict__ b_map,
                const float* __restrict__ W_efc, const float* __restrict__ b_efc,
                float* __restrict__ out)
{
    int tid = threadIdx.x;
    int blk = blockIdx.x;

    // ---- Er head: one thread per batch ----
    {
        int b = blk * 256 + tid;
        if (b < NBATCH) {
            float ey = ego_y[b];
            float dy[4] = { 13.55f - ey, 17.45f - ey, 21.12f - ey, 24.91f - ey };
            float z[4];
            #pragma unroll
            for (int o = 0; o < 4; o++) {
                float a = __ldg(b_sel + o);
                #pragma unroll
                for (int i = 0; i < 4; i++) a = fmaf(dy[i], __ldg(W_sel + o*4+i), a);
                z[o] = a;
            }
            float m = fmaxf(fmaxf(z[0], z[1]), fmaxf(z[2], z[3]));
            float e[4], ssum = 0.f;
            #pragma unroll
            for (int i = 0; i < 4; i++) { e[i] = expf(z[i] - m); ssum += e[i]; }
            float x[4];
            #pragma unroll
            for (int i = 0; i < 4; i++) x[i] = (e[i] / ssum) * dy[i];

            float f[48];
            #pragma unroll
            for (int i = 0; i < 4; i++) f[i] = x[i];
            #pragma unroll
            for (int j = 0; j < 8; j++) {
                float arg = __ldg(b_s0 + j);
                #pragma unroll
                for (int i = 0; i < 4; i++) arg = fmaf(x[i], __ldg(W_s0 + j*4+i), arg);
                float s = my_sinf(arg) + EPSF;
                f[4 + j] = s;
                f[28 + j] = 1.0f / s;
            }
            #pragma unroll
            for (int i = 0; i < 4; i++) {
                float sq = x[i]*x[i] + EPSF;
                float cb = x[i]*x[i]*x[i] + EPSF;
                float ex = __expf(x[i]) + EPSF;
                f[12+i] = sq;           f[36+i] = 1.0f / sq;
                f[16+i] = cb;           f[40+i] = 1.0f / cb;
                f[20+i] = ex;           f[44+i] = 1.0f / ex;
                f[24+i] = 1.0f / (x[i] + EPSF);
            }
            float y[8];
            #pragma unroll
            for (int o = 0; o < 8; o++) {
                float a = __ldg(b_map + o);
                #pragma unroll
                for (int k = 0; k < 48; k++) a = fmaf(f[k], __ldg(W_map + o*48+k), a);
                y[o] = leaky_f(a);
            }
            float r0 = __ldg(b_efc), r1 = __ldg(b_efc + 1);
            #pragma unroll
            for (int k = 0; k < 8; k++) {
                r0 = fmaf(y[k], __ldg(W_efc + k),     r0);
                r1 = fmaf(y[k], __ldg(W_efc + 8 + k), r1);
            }
            out[b*4 + 0] = r0;
            out[b*4 + 1] = r1;
        }
    }

    // ---- softmax over neighbors: 1 warp per batch ----
    {
        int w = tid >> 5, l = tid & 31;
        int b = blk * 8 + w;
        int base = b * 64;
        float v0 = g_lg[base + l], v1 = g_lg[base + 32 + l];
        float m = fmaxf(v0, v1);
        #pragma unroll
        for (int off = 16; off; off >>= 1)
            m = fmaxf(m, __shfl_xor_sync(0xffffffffu, m, off));
        float e0 = expf(v0 - m), e1 = expf(v1 - m);
        float s  = e0 + e1;
        float n0 = e0 * g_en[(base+l)*2]     + e1 * g_en[(base+32+l)*2];
        float n1 = e0 * g_en[(base+l)*2 + 1] + e1 * g_en[(base+32+l)*2 + 1];
        #pragma unroll
        for (int off = 16; off; off >>= 1) {
            s  += __shfl_xor_sync(0xffffffffu, s,  off);
            n0 += __shfl_xor_sync(0xffffffffu, n0, off);
            n1 += __shfl_xor_sync(0xffffffffu, n1, off);
        }
        if (l == 0) {
            out[b*4 + 2] = n0 / s;
            out[b*4 + 3] = n1 / s;
        }
    }
}

// ---------------------------------------------------------------------------
extern "C" void kernel_launch(void* const* d_in, const int* in_sizes, int n_in,
                              void* d_out, int out_size)
{
    const float* ego_y = (const float*)d_in[0];
    const float* Pn    = (const float*)d_in[1];
    const float* Pego  = (const float*)d_in[2];
    const float* Vn    = (const float*)d_in[3];
    const float* Vego  = (const float*)d_in[4];
    const float* Cn    = (const float*)d_in[5];
    const float* W_sel = (const float*)d_in[6];
    const float* b_sel = (const float*)d_in[7];
    const float* W_s0  = (const float*)d_in[8];
    const float* b_s0  = (const float*)d_in[9];
    const float* W_map = (const float*)d_in[10];
    const float* b_map = (const float*)d_in[11];
    const float* W_efc = (const float*)d_in[12];
    const float* b_efc = (const float*)d_in[13];
    const float* W_s1  = (const float*)d_in[14];
    const float* b_s1  = (const float*)d_in[15];
    const float* W1    = (const float*)d_in[16];
    const float* b1    = (const float*)d_in[17];
    const float* W2    = (const float*)d_in[18];
    const float* b2    = (const float*)d_in[19];
    const float* W3    = (const float*)d_in[20];
    const float* b3    = (const float*)d_in[21];
    const float* Ww    = (const float*)d_in[22];
    const float* bw    = (const float*)d_in[23];
    float* out = (float*)d_out;

    size_t smem_bytes = (size_t)SM_TOT * sizeof(float);
    cudaFuncSetAttribute(en_kernel, cudaFuncAttributeMaxDynamicSharedMemorySize,
                         (int)smem_bytes);

    repack_kernel<<<136, 256>>>(W1, W2);
    en_kernel<<<NBATCH * 2, 128, smem_bytes>>>(
        Pn, Pego, Vn, Vego, Cn, W_s1, b_s1, b1, b2, W3, b3, Ww, bw);
    finalize_kernel<<<NBATCH / 8, 256>>>(
        ego_y, W_sel, b_sel, W_s0, b_s0, W_map, b_map, W_efc, b_efc, out);
}

// round 16
// speedup vs baseline: 1.1614x; 1.1614x over previous
#include <cuda_runtime.h>
#include <math.h>
#include <stdint.h>

#define EPSF 1e-6f
#define NBATCH 4096
#define RS3 32            // row stride for 32-row tiles

// k-major repacked weights + one zero pad-chunk (1024 floats) each for
// unconditional depth-1 chunk prefetch. W1 padded to 120 k-rows.
__device__ float g_W1c[120 * 256 + 1024];
__device__ float g_W2c[256 * 128 + 1024];
// En / logit scratch (softmax done in finalize kernel)
__device__ float g_en[NBATCH * 64 * 2];
__device__ float g_lg[NBATCH * 64];

// ---------------------------------------------------------------------------
__device__ __forceinline__ float2 ffma2(float2 a, float2 b, float2 c) {
    float2 d;
    asm("fma.rn.f32x2 %0, %1, %2, %3;"
        : "=l"(reinterpret_cast<unsigned long long&>(d))
        : "l"(reinterpret_cast<unsigned long long&>(a)),
          "l"(reinterpret_cast<unsigned long long&>(b)),
          "l"(reinterpret_cast<unsigned long long&>(c)));
    return d;
}

__device__ __forceinline__ float my_sinf(float x) {
    float k = rintf(x * 0.318309886183790672f);
    float r = fmaf(k, -3.14159274101257324f, x);
    r = fmaf(k, 8.742278012618954e-8f, r);
    float r2 = r * r;
    float p = -2.50521083854e-08f;
    p = fmaf(p, r2, 2.75573192239e-06f);
    p = fmaf(p, r2, -1.98412698413e-04f);
    p = fmaf(p, r2, 8.33333333333e-03f);
    p = fmaf(p, r2, -1.66666666667e-01f);
    float s = fmaf(p * r2, r, r);
    int ki = __float2int_rn(k);
    return (ki & 1) ? -s : s;
}

__device__ __forceinline__ float leaky_f(float x) { return x >= 0.f ? x : 0.1f * x; }

// ---------------------------------------------------------------------------
__global__ void repack_kernel(const float* __restrict__ W1,
                              const float* __restrict__ W2)
{
    int idx = blockIdx.x * 256 + threadIdx.x;
    if (idx < 120 * 256 + 1024) {
        int k = idx >> 8, o = idx & 255;
        g_W1c[idx] = (k < 114) ? W1[o * 114 + k] : 0.f;
    }
    if (idx < 256 * 128 + 1024) {
        int k = idx >> 7, o = idx & 127;
        g_W2c[idx] = (k < 256) ? W2[o * 256 + k] : 0.f;
    }
}

// ---------------------------------------------------------------------------
// feature helpers (stride RS3)
// ---------------------------------------------------------------------------
__device__ __forceinline__ void aug_poly(float* __restrict__ Acol, int base,
                                         float dx, float dy)
{
    Acol[(base+0)*RS3] = dx;
    Acol[(base+1)*RS3] = dy;
    float sqx = dx*dx + EPSF, sqy = dy*dy + EPSF;
    float cbx = dx*dx*dx + EPSF, cby = dy*dy*dy + EPSF;
    float exx = __expf(dx) + EPSF, exy = __expf(dy) + EPSF;
    Acol[(base+19)*RS3] = sqx;  Acol[(base+20)*RS3] = sqy;
    Acol[(base+21)*RS3] = cbx;  Acol[(base+22)*RS3] = cby;
    Acol[(base+23)*RS3] = exx;  Acol[(base+24)*RS3] = exy;
    Acol[(base+25)*RS3] = 1.0f / (dx + EPSF);
    Acol[(base+26)*RS3] = 1.0f / (dy + EPSF);
    Acol[(base+44)*RS3] = 1.0f / sqx;  Acol[(base+45)*RS3] = 1.0f / sqy;
    Acol[(base+46)*RS3] = 1.0f / cbx;  Acol[(base+47)*RS3] = 1.0f / cby;
    Acol[(base+48)*RS3] = 1.0f / exx;  Acol[(base+49)*RS3] = 1.0f / exy;
}

__device__ __forceinline__ void aug_sin(float* __restrict__ Acol, int base,
                                        float dx, float dy,
                                        const float* __restrict__ W_s1,
                                        const float* __restrict__ b_s1,
                                        int j0, int j1)
{
    #pragma unroll 1
    for (int j = j0; j < j1; j++) {
        float arg = fmaf(dx, __ldg(W_s1 + 2*j),
                    fmaf(dy, __ldg(W_s1 + 2*j + 1), __ldg(b_s1 + j)));
        float s = my_sinf(arg) + EPSF;
        Acol[(base+2+j)*RS3]  = s;
        Acol[(base+27+j)*RS3] = 1.0f / s;
    }
}

// ---------------------------------------------------------------------------
// WARP-STAGED GEMM (32-row tile, 128 threads). Each warp consumes a disjoint
// 4*TO-out column slice of every weight chunk, so it stages ONLY its slice
// into a warp-private double buffer and syncs with __syncwarp() — no block
// barriers in the mainloop.
//   rt = tid&7 owns rows 4rt..4rt+3 (1 LDS.128/k)
//   ot = tid>>3 in [0,16): outs ot*TO..+TO-1; warp wid owns ot in [4wid,4wid+4)
// Chunk = CH k-rows; warp slice = CH * 4*TO floats = 256 (2 float4/lane).
// Wg has one zero pad-chunk for unconditional depth-1 prefetch.
// ---------------------------------------------------------------------------
template<int KP, int TO, int CH, int LDWC>
__device__ __forceinline__ void gemm_ws(const float* At,
                                        const float* __restrict__ Wg,
                                        const float* __restrict__ bg,
                                        float* Ct,
                                        float* __restrict__ wbuf,
                                        int rt, int ot, int tid)
{
    constexpr int NC = KP / CH;
    constexpr int SW = 4 * TO;          // slice width in floats (64 / 32)
    constexpr int SB = CH * SW;         // slice floats per buffer (=256)
    int wid  = tid >> 5;
    int lane = tid & 31;
    int ow   = (tid >> 3) & 3;          // ot index within warp

    float* wbw = wbuf + wid * (2 * SB); // warp-private double buffer

    // lane -> (k-row, col4) within slice, for the 2 stage float4s
    // f = s*32 + lane; kr = f / TO; c4 = f % TO
    const float* Wslice = Wg + wid * SW;

    float2 acc[2][TO];
    #pragma unroll
    for (int i = 0; i < TO; i++) {
        float bo = __ldg(bg + ot*TO + i);
        acc[0][i] = make_float2(bo, bo);
        acc[1][i] = make_float2(bo, bo);
    }

    // prologue: stage chunk 0 slice
    #pragma unroll
    for (int s = 0; s < 2; s++) {
        int f  = s*32 + lane;
        int kr = f / TO, c4 = f % TO;
        float4 st = __ldg(reinterpret_cast<const float4*>(
                          Wslice + kr*LDWC + 4*c4));
        *reinterpret_cast<float4*>(wbw + kr*SW + 4*c4) = st;
    }
    __syncwarp();

    #pragma unroll 1
    for (int c = 0; c < NC; c++) {
        // prefetch chunk c+1 slice (pad-chunk on last iter; zeros)
        float4 nx[2];
        #pragma unroll
        for (int s = 0; s < 2; s++) {
            int f  = s*32 + lane;
            int kr = f / TO, c4 = f % TO;
            nx[s] = __ldg(reinterpret_cast<const float4*>(
                          Wslice + ((c+1)*CH + kr)*LDWC + 4*c4));
        }

        const float* wb = wbw + (c & 1)*SB + ow*TO;
        const float* xk = At + (c*CH)*RS3 + 4*rt;

        #pragma unroll
        for (int k = 0; k < CH; k++) {
            float4 xv = *reinterpret_cast<const float4*>(xk + k*RS3);
            float w[TO];
            #pragma unroll
            for (int i = 0; i < TO/4; i++) {
                float4 t = *reinterpret_cast<const float4*>(wb + k*SW + 4*i);
                w[4*i+0] = t.x; w[4*i+1] = t.y; w[4*i+2] = t.z; w[4*i+3] = t.w;
            }
            float2 p0 = make_float2(xv.x, xv.y);
            float2 p1 = make_float2(xv.z, xv.w);
            #pragma unroll
            for (int i = 0; i < TO; i++) {
                float2 ws = make_float2(w[i], w[i]);
                acc[0][i] = ffma2(p0, ws, acc[0][i]);
                acc[1][i] = ffma2(p1, ws, acc[1][i]);
            }
        }

        // store next chunk slice into the other buffer; warp-local handoff
        #pragma unroll
        for (int s = 0; s < 2; s++) {
            int f  = s*32 + lane;
            int kr = f / TO, c4 = f % TO;
            *reinterpret_cast<float4*>(wbw + ((c+1) & 1)*SB + kr*SW + 4*c4) = nx[s];
        }
        __syncwarp();
    }

    // epilogue: leaky + 1 STS.128 per out
    #pragma unroll
    for (int i = 0; i < TO; i++) {
        float4 v;
        v.x = leaky_f(acc[0][i].x);
        v.y = leaky_f(acc[0][i].y);
        v.z = leaky_f(acc[1][i].x);
        v.w = leaky_f(acc[1][i].y);
        *reinterpret_cast<float4*>(Ct + (ot*TO + i)*RS3 + 4*rt) = v;
    }
}

// smem layout (floats): At (features 120x32 = 3840, layer3 partials later),
// h1T 256x32 = 8192 (h2T 128x32 overlays it in layer2 epilogue),
// wbuf 4 warps x 2 x 256 = 2048. Total 14080 floats = 56320 B -> 4 CTAs/SM.
#define SM_A    0
#define SM_H1   3840
#define SM_WB   (SM_H1 + 8192)
#define SM_TOT  (SM_WB + 2048)

__global__ void __launch_bounds__(128, 4)
en_kernel(const float* __restrict__ Pn,  const float* __restrict__ Pego,
          const float* __restrict__ Vn,  const float* __restrict__ Vego,
          const float* __restrict__ Cn,
          const float* __restrict__ W_s1, const float* __restrict__ b_s1,
          const float* __restrict__ b1,
          const float* __restrict__ b2,
          const float* __restrict__ W3,  const float* __restrict__ b3,
          const float* __restrict__ Ww,  const float* __restrict__ bw)
{
    extern __shared__ float sm[];
    float* At   = sm + SM_A;
    float* h1T  = sm + SM_H1;     // h1; h2T overlays after layer2
    float* wbuf = sm + SM_WB;

    int tid = threadIdx.x;
    int blk = blockIdx.x;          // 32-row tile: rows [blk*32, blk*32+32)

    // ---- phase 0: features, 4 threads per row ----
    {
        int r = tid >> 2;          // local row 0..31
        int part = tid & 3;
        int gr = blk*32 + r;       // global row = b*64 + n
        int b = gr >> 6;
        int idx2 = gr * 2;
        float* Acol = At + r;
        if (part < 2) {
            float pex = Pego[b*2], pey = Pego[b*2+1];
            float pnx = Pn[idx2],  pny = Pn[idx2+1];
            float dx = pnx - pex,  dy = pny - pey;
            if (part == 0) {
                Acol[0*RS3] = pex;  Acol[1*RS3] = pey;
                Acol[2*RS3] = pnx;  Acol[3*RS3] = pny;
                Acol[4*RS3] = dx;   Acol[5*RS3] = dy;
                Acol[112*RS3] = Cn[idx2];
                Acol[113*RS3] = Cn[idx2+1];
                aug_poly(Acol, 6, dx, dy);
                aug_sin(Acol, 6, dx, dy, W_s1, b_s1, 0, 9);
            } else {
                aug_sin(Acol, 6, dx, dy, W_s1, b_s1, 9, 17);
            }
        } else {
            float vex = Vego[b*2], vey = Vego[b*2+1];
            float vnx = Vn[idx2],  vny = Vn[idx2+1];
            float dx = vnx - vex,  dy = vny - vey;
            if (part == 2) {
                Acol[56*RS3] = vex;  Acol[57*RS3] = vey;
                Acol[58*RS3] = vnx;  Acol[59*RS3] = vny;
                Acol[60*RS3] = dx;   Acol[61*RS3] = dy;
                aug_poly(Acol, 62, dx, dy);
                aug_sin(Acol, 62, dx, dy, W_s1, b_s1, 0, 9);
            } else {
                aug_sin(Acol, 62, dx, dy, W_s1, b_s1, 9, 17);
            }
        }
        // zero pad rows 114..119 (6*32 = 192 entries, contiguous)
        for (int i = tid; i < 192; i += 128)
            At[114*RS3 + i] = 0.f;
    }
    __syncthreads();

    int rt = tid & 7;      // 8 row-groups (4 rows each)
    int ot = tid >> 3;     // 16 out-groups

    // ---- layer1: [32,114(+6 pad)] -> [32,256], leaky (TO=16, CH=4) ----
    gemm_ws<120, 16, 4, 256>(At, g_W1c, b1, h1T, wbuf, rt, ot, tid);
    __syncthreads();

    // ---- layer2: [32,256] -> [32,128], leaky (TO=8, CH=8); h2T overlays h1T ----
    gemm_ws<256, 8, 8, 128>(h1T, g_W2c, b2, h1T, wbuf, rt, ot, tid);
    __syncthreads();

    // ---- layer3: 128 threads (4 k-segments x 32 rows), partials in At ----
    {
        int seg = tid >> 5;        // 0..3
        int r   = tid & 31;
        int k0  = seg * 32;
        float a0 = 0.f, a1 = 0.f;
        #pragma unroll 8
        for (int k = k0; k < k0 + 32; k++) {
            float h = h1T[k*RS3 + r];
            a0 = fmaf(h, __ldg(W3 + k),       a0);
            a1 = fmaf(h, __ldg(W3 + 128 + k), a1);
        }
        At[(seg*32 + r)*2]     = a0;
        At[(seg*32 + r)*2 + 1] = a1;
    }
    __syncthreads();

    // ---- layer3 reduce + logits -> global scratch ----
    if (tid < 32) {
        int r = tid;
        float a0 = __ldg(b3), a1 = __ldg(b3 + 1);
        #pragma unroll
        for (int seg = 0; seg < 4; seg++) {
            a0 += At[(seg*32 + r)*2];
            a1 += At[(seg*32 + r)*2 + 1];
        }
        int gr = blk*32 + r;
        int b = gr >> 6;
        int idx2 = gr * 2;
        float pnx = Pn[idx2], pny = Pn[idx2+1];
        float dx = pnx - Pego[b*2], dy = pny - Pego[b*2+1];
        float lg = __ldg(bw);
        lg = fmaf(__ldg(Ww+0), a0,  lg);
        lg = fmaf(__ldg(Ww+1), a1,  lg);
        lg = fmaf(__ldg(Ww+2), pnx, lg);
        lg = fmaf(__ldg(Ww+3), pny, lg);
        lg = fmaf(__ldg(Ww+4), dx,  lg);
        lg = fmaf(__ldg(Ww+5), dy,  lg);
        g_en[gr*2]     = a0;
        g_en[gr*2 + 1] = a1;
        g_lg[gr]       = lg;
    }
}

// ---------------------------------------------------------------------------
// finalize: per-batch softmax over 64 neighbors (1 warp/batch) + Er head
// ---------------------------------------------------------------------------
__global__ void __launch_bounds__(256)
finalize_kernel(const float* __restrict__ ego_y,
                const float* __restrict__ W_sel, const float* __restrict__ b_sel,
                const float* __restrict__ W_s0,  const float* __restrict__ b_s0,
                const float* __restrict__ W_map, const float* __restrict__ b_map,
                const float* __restrict__ W_efc, const float* __restrict__ b_efc,
                float* __restrict__ out)
{
    int tid = threadIdx.x;
    int blk = blockIdx.x;

    // ---- Er head: one thread per batch ----
    {
        int b = blk * 256 + tid;
        if (b < NBATCH) {
            float ey = ego_y[b];
            float dy[4] = { 13.55f - ey, 17.45f - ey, 21.12f - ey, 24.91f - ey };
            float z[4];
            #pragma unroll
            for (int o = 0; o < 4; o++) {
                float a = __ldg(b_sel + o);
                #pragma unroll
                for (int i = 0; i < 4; i++) a = fmaf(dy[i], __ldg(W_sel + o*4+i), a);
                z[o] = a;
            }
            float m = fmaxf(fmaxf(z[0], z[1]), fmaxf(z[2], z[3]));
            float e[4], ssum = 0.f;
            #pragma unroll
            for (int i = 0; i < 4; i++) { e[i] = expf(z[i] - m); ssum += e[i]; }
            float x[4];
            #pragma unroll
            for (int i = 0; i < 4; i++) x[i] = (e[i] / ssum) * dy[i];

            float f[48];
            #pragma unroll
            for (int i = 0; i < 4; i++) f[i] = x[i];
            #pragma unroll
            for (int j = 0; j < 8; j++) {
                float arg = __ldg(b_s0 + j);
                #pragma unroll
                for (int i = 0; i < 4; i++) arg = fmaf(x[i], __ldg(W_s0 + j*4+i), arg);
                float s = my_sinf(arg) + EPSF;
                f[4 + j] = s;
                f[28 + j] = 1.0f / s;
            }
            #pragma unroll
            for (int i = 0; i < 4; i++) {
                float sq = x[i]*x[i] + EPSF;
                float cb = x[i]*x[i]*x[i] + EPSF;
                float ex = __expf(x[i]) + EPSF;
                f[12+i] = sq;           f[36+i] = 1.0f / sq;
                f[16+i] = cb;           f[40+i] = 1.0f / cb;
                f[20+i] = ex;           f[44+i] = 1.0f / ex;
                f[24+i] = 1.0f / (x[i] + EPSF);
            }
            float y[8];
            #pragma unroll
            for (int o = 0; o < 8; o++) {
                float a = __ldg(b_map + o);
                #pragma unroll
                for (int k = 0; k < 48; k++) a = fmaf(f[k], __ldg(W_map + o*48+k), a);
                y[o] = leaky_f(a);
            }
            float r0 = __ldg(b_efc), r1 = __ldg(b_efc + 1);
            #pragma unroll
            for (int k = 0; k < 8; k++) {
                r0 = fmaf(y[k], __ldg(W_efc + k),     r0);
                r1 = fmaf(y[k], __ldg(W_efc + 8 + k), r1);
            }
            out[b*4 + 0] = r0;
            out[b*4 + 1] = r1;
        }
    }

    // ---- softmax over neighbors: 1 warp per batch ----
    {
        int w = tid >> 5, l = tid & 31;
        int b = blk * 8 + w;
        int base = b * 64;
        float v0 = g_lg[base + l], v1 = g_lg[base + 32 + l];
        float m = fmaxf(v0, v1);
        #pragma unroll
        for (int off = 16; off; off >>= 1)
            m = fmaxf(m, __shfl_xor_sync(0xffffffffu, m, off));
        float e0 = expf(v0 - m), e1 = expf(v1 - m);
        float s  = e0 + e1;
        float n0 = e0 * g_en[(base+l)*2]     + e1 * g_en[(base+32+l)*2];
        float n1 = e0 * g_en[(base+l)*2 + 1] + e1 * g_en[(base+32+l)*2 + 1];
        #pragma unroll
        for (int off = 16; off; off >>= 1) {
            s  += __shfl_xor_sync(0xffffffffu, s,  off);
            n0 += __shfl_xor_sync(0xffffffffu, n0, off);
            n1 += __shfl_xor_sync(0xffffffffu, n1, off);
        }
        if (l == 0) {
            out[b*4 + 2] = n0 / s;
            out[b*4 + 3] = n1 / s;
        }
    }
}

// ---------------------------------------------------------------------------
extern "C" void kernel_launch(void* const* d_in, const int* in_sizes, int n_in,
                              void* d_out, int out_size)
{
    const float* ego_y = (const float*)d_in[0];
    const float* Pn    = (const float*)d_in[1];
    const float* Pego  = (const float*)d_in[2];
    const float* Vn    = (const float*)d_in[3];
    const float* Vego  = (const float*)d_in[4];
    const float* Cn    = (const float*)d_in[5];
    const float* W_sel = (const float*)d_in[6];
    const float* b_sel = (const float*)d_in[7];
    const float* W_s0  = (const float*)d_in[8];
    const float* b_s0  = (const float*)d_in[9];
    const float* W_map = (const float*)d_in[10];
    const float* b_map = (const float*)d_in[11];
    const float* W_efc = (const float*)d_in[12];
    const float* b_efc = (const float*)d_in[13];
    const float* W_s1  = (const float*)d_in[14];
    const float* b_s1  = (const float*)d_in[15];
    const float* W1    = (const float*)d_in[16];
    const float* b1    = (const float*)d_in[17];
    const float* W2    = (const float*)d_in[18];
    const float* b2    = (const float*)d_in[19];
    const float* W3    = (const float*)d_in[20];
    const float* b3    = (const float*)d_in[21];
    const float* Ww    = (const float*)d_in[22];
    const float* bw    = (const float*)d_in[23];
    float* out = (float*)d_out;

    size_t smem_bytes = (size_t)SM_TOT * sizeof(float);
    cudaFuncSetAttribute(en_kernel, cudaFuncAttributeMaxDynamicSharedMemorySize,
                         (int)smem_bytes);

    repack_kernel<<<132, 256>>>(W1, W2);
    en_kernel<<<NBATCH * 2, 128, smem_bytes>>>(
        Pn, Pego, Vn, Vego, Cn, W_s1, b_s1, b1, b2, W3, b3, Ww, bw);
    finalize_kernel<<<NBATCH / 8, 256>>>(
        ego_y, W_sel, b_sel, W_s0, b_s0, W_map, b_map, W_efc, b_efc, out);
}